// round 2
// baseline (speedup 1.0000x reference)
#include <cuda_runtime.h>
#include <math.h>

#define BATCH 16
#define H 512
#define W 512
#define HW (H*W)

typedef unsigned long long ull;

// Global scratch (allocation-free rule): two ping-pong feature buffers,
// 24 channels each ([0:12) = filter branch, [12:24) = weight branch).
__device__ float g_bufA[(size_t)BATCH * 24 * HW];
__device__ float g_bufB[(size_t)BATCH * 24 * HW];

// ---- packed f32x2 helpers ------------------------------------------------
__device__ __forceinline__ void fma2(ull& d, ull a, ull b) {
    asm("fma.rn.f32x2 %0, %1, %2, %0;" : "+l"(d) : "l"(a), "l"(b));
}
__device__ __forceinline__ ull bcast2(float v) {
    ull r; unsigned u = __float_as_uint(v);
    asm("mov.b64 %0, {%1, %1};" : "=l"(r) : "r"(u));
    return r;
}
__device__ __forceinline__ void unpack2(float& lo, float& hi, ull d) {
    unsigned a, b;
    asm("mov.b64 {%0, %1}, %2;" : "=r"(a), "=r"(b) : "l"(d));
    lo = __uint_as_float(a); hi = __uint_as_float(b);
}

// ---------------------------------------------------------------------------
// Grouped 3x3 conv, SAME padding, ReLU. CIN in-channels per group, 12 out.
// gridDim.z = BATCH*2 ; group g = z&1 selects weight set (wA / wB).
// Tile: 64 wide x 8 high. Block (16,8): each thread does 4 pixels x 12 cout.
// Accumulation uses fma.rn.f32x2 packed across cout pairs (half the fma-pipe
// issue count vs scalar FFMA). Weights reordered cout-minor in shared so a
// single LDS.64 yields a packed cout pair.
// inSel/outSel: 0 = external pointer, 1 = g_bufA, 2 = g_bufB.
// ---------------------------------------------------------------------------
template<int CIN>
__global__ void __launch_bounds__(128, 4)
conv3x3_kernel(const float* __restrict__ extIn, int inSel, int inC, int inGroupStride,
               int outSel,
               const float* __restrict__ wA, const float* __restrict__ wB)
{
    constexpr int TW = 64, TH = 8, PX = 4, PITCH = 68;

    __shared__ __align__(16) float s_in[CIN][TH + 2][PITCH];
    __shared__ __align__(8) float s_w[CIN * 9 * 12];   // [ci*9+k][cout]

    const int g = blockIdx.z & 1;
    const int b = blockIdx.z >> 1;

    const float* inBase = (inSel == 1) ? g_bufA : ((inSel == 2) ? g_bufB : extIn);
    float* outBase = (outSel == 1) ? g_bufA : g_bufB;

    const float* __restrict__ wt = g ? wB : wA;
    const float* __restrict__ inp = inBase + ((size_t)b * inC + (size_t)g * inGroupStride) * HW;
    float* __restrict__ outp = outBase + ((size_t)b * 24 + (size_t)g * 12) * HW;

    const int tid = threadIdx.y * 16 + threadIdx.x;

    // weights to shared, transposed to cout-minor: s_w[rest*12+co] = wt[co*CIN*9+rest]
    for (int i = tid; i < 12 * CIN * 9; i += 128) {
        int co = i % 12;
        int rest = i / 12;
        s_w[i] = wt[co * CIN * 9 + rest];
    }

    // input tile (with 1-halo), zero-padded at image borders
    const int x0 = blockIdx.x * TW - 1;
    const int y0 = blockIdx.y * TH - 1;
    for (int i = tid; i < CIN * (TH + 2) * 66; i += 128) {
        int c  = i / ((TH + 2) * 66);
        int r  = i - c * ((TH + 2) * 66);
        int iy = r / 66;
        int ix = r - iy * 66;
        int gy = y0 + iy, gx = x0 + ix;
        float v = 0.0f;
        if ((unsigned)gy < (unsigned)H && (unsigned)gx < (unsigned)W)
            v = inp[(size_t)c * HW + (size_t)gy * W + gx];
        s_in[c][iy][ix] = v;
    }
    __syncthreads();

    // acc2[p][c]: lanes = (cout 2c, cout 2c+1) for pixel p
    ull acc2[PX][6];
#pragma unroll
    for (int p = 0; p < PX; ++p)
#pragma unroll
        for (int c = 0; c < 6; ++c) acc2[p][c] = 0ULL;

    const int bx = threadIdx.x * PX;
    const int ty = threadIdx.y;

    for (int ci = 0; ci < CIN; ++ci) {
#pragma unroll
        for (int ky = 0; ky < 3; ++ky) {
            const float* row = &s_in[ci][ty + ky][bx];
            float4 va = *(const float4*)row;
            float2 vb = *(const float2*)(row + 4);
            ull bb[6];
            bb[0] = bcast2(va.x); bb[1] = bcast2(va.y); bb[2] = bcast2(va.z);
            bb[3] = bcast2(va.w); bb[4] = bcast2(vb.x); bb[5] = bcast2(vb.y);
#pragma unroll
            for (int kx = 0; kx < 3; ++kx) {
                const ull* wp = (const ull*)&s_w[(ci * 9 + ky * 3 + kx) * 12];
                ull w0 = wp[0], w1 = wp[1], w2 = wp[2], w3 = wp[3], w4 = wp[4], w5 = wp[5];
#pragma unroll
                for (int p = 0; p < PX; ++p) {
                    ull v = bb[kx + p];
                    fma2(acc2[p][0], v, w0);
                    fma2(acc2[p][1], v, w1);
                    fma2(acc2[p][2], v, w2);
                    fma2(acc2[p][3], v, w3);
                    fma2(acc2[p][4], v, w4);
                    fma2(acc2[p][5], v, w5);
                }
            }
        }
    }

    const int oy = blockIdx.y * TH + ty;
    const int ox = blockIdx.x * TW + bx;
#pragma unroll
    for (int c = 0; c < 6; ++c) {
        float4 r0, r1;
        float lo, hi;
        unpack2(lo, hi, acc2[0][c]); r0.x = fmaxf(lo, 0.f); r1.x = fmaxf(hi, 0.f);
        unpack2(lo, hi, acc2[1][c]); r0.y = fmaxf(lo, 0.f); r1.y = fmaxf(hi, 0.f);
        unpack2(lo, hi, acc2[2][c]); r0.z = fmaxf(lo, 0.f); r1.z = fmaxf(hi, 0.f);
        unpack2(lo, hi, acc2[3][c]); r0.w = fmaxf(lo, 0.f); r1.w = fmaxf(hi, 0.f);
        *(float4*)&outp[(size_t)(2 * c)     * HW + (size_t)oy * W + ox] = r0;
        *(float4*)&outp[(size_t)(2 * c + 1) * HW + (size_t)oy * W + ox] = r1;
    }
}

// ---------------------------------------------------------------------------
// Fusion: softmax over weight channels, green interpolation, chroma conv
// (2->6, SAME), green_add, pixel-shuffle to [B,3,1024,1024].
// Tile 32x8 output pixels, 1-pixel halo for the chroma conv.
// ---------------------------------------------------------------------------
__global__ void __launch_bounds__(256, 4)
fuse_kernel(int featSel, const float* __restrict__ mosaic,
            const float* __restrict__ cw, float* __restrict__ out)
{
    __shared__ float s_g0[10][36];
    __shared__ float s_g1[10][36];
    __shared__ float s_d0[10][36];
    __shared__ float s_d1[10][36];
    __shared__ float s_cw[108];

    const int b = blockIdx.z;
    const float* __restrict__ fp = ((featSel == 1) ? g_bufA : g_bufB) + (size_t)b * 24 * HW;
    const float* __restrict__ mp = mosaic + (size_t)b * 4 * HW;

    const int tid = threadIdx.y * 32 + threadIdx.x;
    if (tid < 108) s_cw[tid] = cw[tid];

    const int x0 = blockIdx.x * 32 - 1;
    const int y0 = blockIdx.y * 8 - 1;

    // Stage 1: green (g0, g1) and chroma-conv inputs (d0, d1) over 34x10 region
    for (int i = tid; i < 34 * 10; i += 256) {
        int iy = i / 34;
        int ix = i - iy * 34;
        int gy = y0 + iy, gx = x0 + ix;
        float g0 = 0.f, g1 = 0.f, d0 = 0.f, d1 = 0.f;
        if ((unsigned)gy < (unsigned)H && (unsigned)gx < (unsigned)W) {
            size_t off = (size_t)gy * W + gx;
            float iv[12], wv[12];
#pragma unroll
            for (int c = 0; c < 12; ++c) iv[c] = fp[(size_t)c * HW + off];
#pragma unroll
            for (int c = 0; c < 12; ++c) wv[c] = fp[(size_t)(12 + c) * HW + off];
            float m = wv[0];
#pragma unroll
            for (int c = 1; c < 12; ++c) m = fmaxf(m, wv[c]);
            float s = 0.f, n0 = 0.f, n1 = 0.f;
#pragma unroll
            for (int c = 0; c < 6; ++c) {
                float e = __expf(wv[c] - m);
                s += e; n0 = fmaf(e, iv[c], n0);
            }
#pragma unroll
            for (int c = 6; c < 12; ++c) {
                float e = __expf(wv[c] - m);
                s += e; n1 = fmaf(e, iv[c], n1);
            }
            float inv = 1.0f / s;
            g0 = n0 * inv;
            g1 = n1 * inv;
            d0 = mp[HW + off] - g0;        // mosaic[1] - green_rb[0]
            d1 = mp[2 * HW + off] - g1;    // mosaic[2] - green_rb[1]
        }
        s_g0[iy][ix] = g0;
        s_g1[iy][ix] = g1;
        s_d0[iy][ix] = d0;
        s_d1[iy][ix] = d1;
    }
    __syncthreads();

    // Stage 2: chroma conv + assembly + pixel shuffle (one center pixel/thread)
    const int tx = threadIdx.x, ty = threadIdx.y;
    const int gx = blockIdx.x * 32 + tx;
    const int gy = blockIdx.y * 8 + ty;

    float cd[6] = {0.f, 0.f, 0.f, 0.f, 0.f, 0.f};
#pragma unroll
    for (int ky = 0; ky < 3; ++ky) {
#pragma unroll
        for (int kx = 0; kx < 3; ++kx) {
            float v0 = s_d0[ty + ky][tx + kx];
            float v1 = s_d1[ty + ky][tx + kx];
#pragma unroll
            for (int o = 0; o < 6; ++o) {
                cd[o] = fmaf(v0, s_cw[(o * 2 + 0) * 9 + ky * 3 + kx], cd[o]);
                cd[o] = fmaf(v1, s_cw[(o * 2 + 1) * 9 + ky * 3 + kx], cd[o]);
            }
        }
    }

    size_t off = (size_t)gy * W + gx;
    float m0 = mp[off];
    float m1 = mp[HW + off];
    float m2 = mp[2 * HW + off];
    float m3 = mp[3 * HW + off];
    float g0 = s_g0[ty + 1][tx + 1];
    float g1 = s_g1[ty + 1][tx + 1];

    // green_add = [m0, g1, m3, m0, g0, m3]
    float cp0 = cd[0] + m0;
    float cp1 = cd[1] + g1;
    float cp2 = cd[2] + m3;
    float cp3 = cd[3] + m0;
    float cp4 = cd[4] + g0;
    float cp5 = cd[5] + m3;

    const size_t OP = (size_t)4 * HW;           // 1024*1024 plane
    float* ob = out + (size_t)b * 3 * OP;
    size_t base = (size_t)(2 * gy) * 1024 + (size_t)(2 * gx);

    // R plane: interleave(cp0, m1, cp1, cp2)
    *(float2*)(ob + 0 * OP + base)        = make_float2(cp0, m1);
    *(float2*)(ob + 0 * OP + base + 1024) = make_float2(cp1, cp2);
    // G plane: interleave(m0, g0, g1, m3)
    *(float2*)(ob + 1 * OP + base)        = make_float2(m0, g0);
    *(float2*)(ob + 1 * OP + base + 1024) = make_float2(g1, m3);
    // B plane: interleave(cp3, cp4, m2, cp5)
    *(float2*)(ob + 2 * OP + base)        = make_float2(cp3, cp4);
    *(float2*)(ob + 2 * OP + base + 1024) = make_float2(m2, cp5);
}

// ---------------------------------------------------------------------------
extern "C" void kernel_launch(void* const* d_in, const int* in_sizes, int n_in,
                              void* d_out, int out_size)
{
    const float* mosaic = (const float*)d_in[0];
    const float* fw0 = (const float*)d_in[1];
    const float* fw1 = (const float*)d_in[2];
    const float* fw2 = (const float*)d_in[3];
    const float* ww0 = (const float*)d_in[4];
    const float* ww1 = (const float*)d_in[5];
    const float* ww2 = (const float*)d_in[6];
    const float* cw0 = (const float*)d_in[7];
    float* out = (float*)d_out;

    dim3 cb(16, 8);
    dim3 cg(W / 64, H / 8, BATCH * 2);

    // layer 0: mosaic(4ch) -> bufA(24ch)   [groups share input, offset 0]
    conv3x3_kernel<4><<<cg, cb>>>(mosaic, /*inSel=*/0, /*inC=*/4, /*inGroupStride=*/0,
                                  /*outSel=*/1, fw0, ww0);
    // layer 1: bufA -> bufB, grouped 12->12
    conv3x3_kernel<12><<<cg, cb>>>(nullptr, /*inSel=*/1, /*inC=*/24, /*inGroupStride=*/12,
                                   /*outSel=*/2, fw1, ww1);
    // layer 2: bufB -> bufA, grouped 12->12
    conv3x3_kernel<12><<<cg, cb>>>(nullptr, /*inSel=*/2, /*inC=*/24, /*inGroupStride=*/12,
                                   /*outSel=*/1, fw2, ww2);
    // fusion + pixel shuffle
    dim3 fb(32, 8);
    dim3 fg(W / 32, H / 8, BATCH);
    fuse_kernel<<<fg, fb>>>(/*featSel=*/1, mosaic, cw0, out);
}